// round 1
// baseline (speedup 1.0000x reference)
#include <cuda_runtime.h>
#include <cuda_bf16.h>
#include <float.h>

// Problem dims (fixed by the reference)
#define NH    8      // heads
#define NSEQ  4096   // sequence length
#define FIN   512    // input features
#define HD    64     // head dim
#define FOUT  512    // output features

// Scratch (device globals: allocation-free rule)
__device__ float g_Q[NH * NSEQ * HD];   // [h][n][d]
__device__ float g_K[NH * NSEQ * HD];
__device__ float g_V[NH * NSEQ * HD];
__device__ float g_C[NSEQ * NH * HD];   // Hcat: [n][h*HD+d]

// ---------------------------------------------------------------------------
// Kernel 1: fused Q/K/V projection. grid = (N/64, H, 3), block = 256.
// Out[h][m][d] = sum_f X[h][m][f] * W[h][d][f]
// ---------------------------------------------------------------------------
__global__ __launch_bounds__(256) void qkv_kernel(
    const float* __restrict__ X,
    const float* __restrict__ Wq,
    const float* __restrict__ Wk,
    const float* __restrict__ Wv)
{
    __shared__ float Xs[64][33];
    __shared__ float Ws[64][33];

    const int h  = blockIdx.y;
    const int m0 = blockIdx.x * 64;
    const float* W   = (blockIdx.z == 0) ? Wq : (blockIdx.z == 1) ? Wk : Wv;
    float*       Out = (blockIdx.z == 0) ? g_Q : (blockIdx.z == 1) ? g_K : g_V;

    const float* Xh = X + (size_t)h * NSEQ * FIN;
    const float* Wh = W + (size_t)h * HD * FIN;

    const int tid = threadIdx.x;
    const int tx = tid & 15;    // output col group (d)
    const int ty = tid >> 4;    // output row group (m)

    float acc[4][4];
    #pragma unroll
    for (int i = 0; i < 4; i++)
        #pragma unroll
        for (int j = 0; j < 4; j++) acc[i][j] = 0.f;

    for (int f0 = 0; f0 < FIN; f0 += 32) {
        // Load 64x32 tiles of X and W (512 float4 each; 2 per thread)
        #pragma unroll
        for (int u = 0; u < 2; u++) {
            int idx = tid * 2 + u;      // 0..511
            int row = idx >> 3;
            int c4  = (idx & 7) * 4;
            float4 xv = *(const float4*)(Xh + (size_t)(m0 + row) * FIN + f0 + c4);
            Xs[row][c4 + 0] = xv.x; Xs[row][c4 + 1] = xv.y;
            Xs[row][c4 + 2] = xv.z; Xs[row][c4 + 3] = xv.w;
            float4 wv = *(const float4*)(Wh + (size_t)row * FIN + f0 + c4);
            Ws[row][c4 + 0] = wv.x; Ws[row][c4 + 1] = wv.y;
            Ws[row][c4 + 2] = wv.z; Ws[row][c4 + 3] = wv.w;
        }
        __syncthreads();

        #pragma unroll
        for (int kk = 0; kk < 32; kk++) {
            float a[4], b[4];
            #pragma unroll
            for (int i = 0; i < 4; i++) a[i] = Xs[ty * 4 + i][kk];
            #pragma unroll
            for (int j = 0; j < 4; j++) b[j] = Ws[tx * 4 + j][kk];
            #pragma unroll
            for (int i = 0; i < 4; i++)
                #pragma unroll
                for (int j = 0; j < 4; j++)
                    acc[i][j] = fmaf(a[i], b[j], acc[i][j]);
        }
        __syncthreads();
    }

    #pragma unroll
    for (int i = 0; i < 4; i++) {
        size_t rbase = ((size_t)h * NSEQ + m0 + ty * 4 + i) * HD + tx * 4;
        #pragma unroll
        for (int j = 0; j < 4; j++)
            Out[rbase + j] = acc[i][j];
    }
}

// ---------------------------------------------------------------------------
// Kernel 2: flash attention, 64x64 tiles, online softmax.
// grid = (N/64, H), block = 256, dynamic smem.
// ---------------------------------------------------------------------------
#define ATTN_SMEM (4 * 64 * 65 * 4)

__global__ __launch_bounds__(256) void attn_kernel(const int* __restrict__ mask)
{
    extern __shared__ float sm[];
    float* Qs = sm;                 // [64][65], pre-scaled by 1/sqrt(HD)
    float* Ks = Qs + 64 * 65;       // [64][65]
    float* Vs = Ks + 64 * 65;       // [64][65]
    float* Ps = Vs + 64 * 65;       // [64][65]

    const int h  = blockIdx.y;
    const int q0 = blockIdx.x * 64;
    const int tid = threadIdx.x;
    const int tx = tid & 15;
    const int ty = tid >> 4;

    // Load Q tile (scaled)
    const float* Qg = g_Q + ((size_t)h * NSEQ + q0) * HD;
    for (int idx = tid; idx < 64 * 64; idx += 256) {
        int r = idx >> 6, c = idx & 63;
        Qs[r * 65 + c] = Qg[(size_t)r * HD + c] * 0.125f;   // 1/sqrt(64)
    }

    float mrow[4], lrow[4], oacc[4][4];
    #pragma unroll
    for (int i = 0; i < 4; i++) {
        mrow[i] = -3.0e38f;
        lrow[i] = 0.f;
        #pragma unroll
        for (int j = 0; j < 4; j++) oacc[i][j] = 0.f;
    }

    for (int k0 = 0; k0 < NSEQ; k0 += 64) {
        __syncthreads();   // protects Ks/Vs/Ps reuse (and first-iter Q load)
        const float* Kg = g_K + ((size_t)h * NSEQ + k0) * HD;
        const float* Vg = g_V + ((size_t)h * NSEQ + k0) * HD;
        for (int idx = tid; idx < 64 * 64; idx += 256) {
            int r = idx >> 6, c = idx & 63;
            Ks[r * 65 + c] = Kg[(size_t)r * HD + c];
            Vs[r * 65 + c] = Vg[(size_t)r * HD + c];
        }
        __syncthreads();

        // S = Qs @ Ks^T  (4x4 micro-tile per thread)
        float s[4][4];
        #pragma unroll
        for (int i = 0; i < 4; i++)
            #pragma unroll
            for (int j = 0; j < 4; j++) s[i][j] = 0.f;

        #pragma unroll 8
        for (int kk = 0; kk < 64; kk++) {
            float a[4], b[4];
            #pragma unroll
            for (int i = 0; i < 4; i++) a[i] = Qs[(ty * 4 + i) * 65 + kk];
            #pragma unroll
            for (int j = 0; j < 4; j++) b[j] = Ks[(tx * 4 + j) * 65 + kk];
            #pragma unroll
            for (int i = 0; i < 4; i++)
                #pragma unroll
                for (int j = 0; j < 4; j++)
                    s[i][j] = fmaf(a[i], b[j], s[i][j]);
        }

        // Apply mask (int4 vectorized load of 4 consecutive mask entries)
        #pragma unroll
        for (int i = 0; i < 4; i++) {
            const int* mp = mask + ((size_t)h * NSEQ + q0 + ty * 4 + i) * NSEQ
                                 + k0 + tx * 4;
            int4 mv = *(const int4*)mp;
            if (mv.x == 0) s[i][0] = -1e30f;
            if (mv.y == 0) s[i][1] = -1e30f;
            if (mv.z == 0) s[i][2] = -1e30f;
            if (mv.w == 0) s[i][3] = -1e30f;
        }

        // Row max across this thread's 4 cols, then across 16 tx lanes
        float mt[4];
        #pragma unroll
        for (int i = 0; i < 4; i++)
            mt[i] = fmaxf(fmaxf(s[i][0], s[i][1]), fmaxf(s[i][2], s[i][3]));
        #pragma unroll
        for (int off = 1; off < 16; off <<= 1)
            #pragma unroll
            for (int i = 0; i < 4; i++)
                mt[i] = fmaxf(mt[i], __shfl_xor_sync(0xffffffffu, mt[i], off));

        float mnew[4], corr[4];
        #pragma unroll
        for (int i = 0; i < 4; i++) {
            mnew[i] = fmaxf(mrow[i], mt[i]);
            corr[i] = __expf(mrow[i] - mnew[i]);   // ->0 when mrow=-3e38
        }

        // p = exp(s - mnew), row-sum reduce
        float rs[4];
        #pragma unroll
        for (int i = 0; i < 4; i++) {
            rs[i] = 0.f;
            #pragma unroll
            for (int j = 0; j < 4; j++) {
                s[i][j] = __expf(s[i][j] - mnew[i]);
                rs[i] += s[i][j];
            }
        }
        #pragma unroll
        for (int off = 1; off < 16; off <<= 1)
            #pragma unroll
            for (int i = 0; i < 4; i++)
                rs[i] += __shfl_xor_sync(0xffffffffu, rs[i], off);

        #pragma unroll
        for (int i = 0; i < 4; i++) {
            lrow[i] = lrow[i] * corr[i] + rs[i];
            mrow[i] = mnew[i];
            #pragma unroll
            for (int j = 0; j < 4; j++) oacc[i][j] *= corr[i];
        }

        // Stage P to smem for the PV GEMM
        #pragma unroll
        for (int i = 0; i < 4; i++)
            #pragma unroll
            for (int j = 0; j < 4; j++)
                Ps[(ty * 4 + i) * 65 + tx * 4 + j] = s[i][j];
        __syncthreads();

        // O += P @ V
        #pragma unroll 8
        for (int kk = 0; kk < 64; kk++) {
            float a[4], b[4];
            #pragma unroll
            for (int i = 0; i < 4; i++) a[i] = Ps[(ty * 4 + i) * 65 + kk];
            #pragma unroll
            for (int j = 0; j < 4; j++) b[j] = Vs[kk * 65 + tx * 4 + j];
            #pragma unroll
            for (int i = 0; i < 4; i++)
                #pragma unroll
                for (int j = 0; j < 4; j++)
                    oacc[i][j] = fmaf(a[i], b[j], oacc[i][j]);
        }
    }

    // Normalize and write Hcat: [n][h*HD + d]
    #pragma unroll
    for (int i = 0; i < 4; i++) {
        float inv_l = 1.f / lrow[i];
        size_t rbase = (size_t)(q0 + ty * 4 + i) * (NH * HD) + h * HD + tx * 4;
        #pragma unroll
        for (int j = 0; j < 4; j++)
            g_C[rbase + j] = oacc[i][j] * inv_l;
    }
}

// ---------------------------------------------------------------------------
// Kernel 3: output projection. out[n][o] = sum_c C[n][c] * Wo[o][c]
// grid = (N/64, FOUT/64), block = 256.
// ---------------------------------------------------------------------------
__global__ __launch_bounds__(256) void proj_kernel(
    const float* __restrict__ Wo, float* __restrict__ out)
{
    __shared__ float Cs[64][33];
    __shared__ float Ws[64][33];

    const int m0 = blockIdx.x * 64;
    const int n0 = blockIdx.y * 64;
    const int tid = threadIdx.x;
    const int tx = tid & 15;
    const int ty = tid >> 4;

    float acc[4][4];
    #pragma unroll
    for (int i = 0; i < 4; i++)
        #pragma unroll
        for (int j = 0; j < 4; j++) acc[i][j] = 0.f;

    for (int f0 = 0; f0 < FIN; f0 += 32) {   // K dim = NH*HD = 512 = FIN
        #pragma unroll
        for (int u = 0; u < 2; u++) {
            int idx = tid * 2 + u;
            int row = idx >> 3;
            int c4  = (idx & 7) * 4;
            float4 cv = *(const float4*)(g_C + (size_t)(m0 + row) * (NH * HD) + f0 + c4);
            Cs[row][c4 + 0] = cv.x; Cs[row][c4 + 1] = cv.y;
            Cs[row][c4 + 2] = cv.z; Cs[row][c4 + 3] = cv.w;
            float4 wv = *(const float4*)(Wo + (size_t)(n0 + row) * (NH * HD) + f0 + c4);
            Ws[row][c4 + 0] = wv.x; Ws[row][c4 + 1] = wv.y;
            Ws[row][c4 + 2] = wv.z; Ws[row][c4 + 3] = wv.w;
        }
        __syncthreads();

        #pragma unroll
        for (int kk = 0; kk < 32; kk++) {
            float a[4], b[4];
            #pragma unroll
            for (int i = 0; i < 4; i++) a[i] = Cs[ty * 4 + i][kk];
            #pragma unroll
            for (int j = 0; j < 4; j++) b[j] = Ws[tx * 4 + j][kk];
            #pragma unroll
            for (int i = 0; i < 4; i++)
                #pragma unroll
                for (int j = 0; j < 4; j++)
                    acc[i][j] = fmaf(a[i], b[j], acc[i][j]);
        }
        __syncthreads();
    }

    #pragma unroll
    for (int i = 0; i < 4; i++) {
        size_t rbase = (size_t)(m0 + ty * 4 + i) * FOUT + n0 + tx * 4;
        #pragma unroll
        for (int j = 0; j < 4; j++)
            out[rbase + j] = acc[i][j];
    }
}

// ---------------------------------------------------------------------------
extern "C" void kernel_launch(void* const* d_in, const int* in_sizes, int n_in,
                              void* d_out, int out_size)
{
    const float* X    = (const float*)d_in[0];
    const int*   mask = (const int*)  d_in[1];
    const float* Wq   = (const float*)d_in[2];
    const float* Wk   = (const float*)d_in[3];
    const float* Wv   = (const float*)d_in[4];
    const float* Wo   = (const float*)d_in[5];
    float*       out  = (float*)d_out;

    cudaFuncSetAttribute(attn_kernel,
                         cudaFuncAttributeMaxDynamicSharedMemorySize, ATTN_SMEM);

    qkv_kernel<<<dim3(NSEQ / 64, NH, 3), 256>>>(X, Wq, Wk, Wv);
    attn_kernel<<<dim3(NSEQ / 64, NH), 256, ATTN_SMEM>>>(mask);
    proj_kernel<<<dim3(NSEQ / 64, FOUT / 64), 256>>>(Wo, out);
}

// round 3
// speedup vs baseline: 3.5101x; 3.5101x over previous
#include <cuda_runtime.h>
#include <cstdint>
#include <cstddef>

// Problem dims
#define NH    8
#define NSEQ  4096
#define FIN   512
#define HD    64
#define FOUT  512

#define QT 128          // query rows per CTA (8 warps x 16)
#define KT 64           // keys per iteration
#define NIT (NSEQ / KT)

// Scratch (device globals: allocation-free rule)
__device__ float g_Q[NH * NSEQ * HD];   // tf32-rounded, pre-scaled by 1/8
__device__ float g_K[NH * NSEQ * HD];   // tf32-rounded
__device__ float g_V[NH * NSEQ * HD];   // tf32-rounded
__device__ float g_C[NSEQ * NH * HD];   // [n][h*HD+d]

__device__ __forceinline__ float to_tf32(float x) {
    float r; asm("cvt.rna.tf32.f32 %0, %1;" : "=f"(r) : "f"(x)); return r;
}

// m16n8k8 tf32 MMA (sm_80+ PTX; maps to HMMA on sm_103)
__device__ __forceinline__ void mma8(float* c, const uint32_t* a, uint32_t b0, uint32_t b1) {
    asm volatile(
        "mma.sync.aligned.m16n8k8.row.col.f32.tf32.tf32.f32 "
        "{%0,%1,%2,%3}, {%4,%5,%6,%7}, {%8,%9}, {%0,%1,%2,%3};"
        : "+f"(c[0]), "+f"(c[1]), "+f"(c[2]), "+f"(c[3])
        : "r"(a[0]), "r"(a[1]), "r"(a[2]), "r"(a[3]), "r"(b0), "r"(b1));
}

// SMEM layout (floats): K[64][68] | V[64][68] | P[128][68]
#define KV_STRIDE 68
#define SM_V  (64 * KV_STRIDE)
#define SM_P  (2 * 64 * KV_STRIDE)
#define ATTN_SMEM_FLOATS (SM_P + 128 * KV_STRIDE)
#define ATTN_SMEM_BYTES  (ATTN_SMEM_FLOATS * 4)

// ---------------------------------------------------------------------------
// Kernel 1: QKV projection (fp32 scalar math, tf32-rounded outputs)
// ---------------------------------------------------------------------------
__global__ __launch_bounds__(256) void qkv_kernel(
    const float* __restrict__ X,
    const float* __restrict__ Wq,
    const float* __restrict__ Wk,
    const float* __restrict__ Wv)
{
    __shared__ float Xs[64][33];
    __shared__ float Ws[64][33];

    const int h  = blockIdx.y;
    const int m0 = blockIdx.x * 64;
    const float* W   = (blockIdx.z == 0) ? Wq : (blockIdx.z == 1) ? Wk : Wv;
    float*       Out = (blockIdx.z == 0) ? g_Q : (blockIdx.z == 1) ? g_K : g_V;
    const float scale = (blockIdx.z == 0) ? 0.125f : 1.0f;   // fold 1/sqrt(64) into Q

    const float* Xh = X + (size_t)h * NSEQ * FIN;
    const float* Wh = W + (size_t)h * HD * FIN;

    const int tid = threadIdx.x;
    const int tx = tid & 15;
    const int ty = tid >> 4;

    float acc[4][4];
    #pragma unroll
    for (int i = 0; i < 4; i++)
        #pragma unroll
        for (int j = 0; j < 4; j++) acc[i][j] = 0.f;

    for (int f0 = 0; f0 < FIN; f0 += 32) {
        #pragma unroll
        for (int u = 0; u < 2; u++) {
            int idx = tid * 2 + u;
            int row = idx >> 3;
            int c4  = (idx & 7) * 4;
            float4 xv = *(const float4*)(Xh + (size_t)(m0 + row) * FIN + f0 + c4);
            Xs[row][c4 + 0] = xv.x; Xs[row][c4 + 1] = xv.y;
            Xs[row][c4 + 2] = xv.z; Xs[row][c4 + 3] = xv.w;
            float4 wv = *(const float4*)(Wh + (size_t)row * FIN + f0 + c4);
            Ws[row][c4 + 0] = wv.x; Ws[row][c4 + 1] = wv.y;
            Ws[row][c4 + 2] = wv.z; Ws[row][c4 + 3] = wv.w;
        }
        __syncthreads();
        #pragma unroll
        for (int kk = 0; kk < 32; kk++) {
            float a[4], b[4];
            #pragma unroll
            for (int i = 0; i < 4; i++) a[i] = Xs[ty * 4 + i][kk];
            #pragma unroll
            for (int j = 0; j < 4; j++) b[j] = Ws[tx * 4 + j][kk];
            #pragma unroll
            for (int i = 0; i < 4; i++)
                #pragma unroll
                for (int j = 0; j < 4; j++)
                    acc[i][j] = fmaf(a[i], b[j], acc[i][j]);
        }
        __syncthreads();
    }

    #pragma unroll
    for (int i = 0; i < 4; i++) {
        size_t rbase = ((size_t)h * NSEQ + m0 + ty * 4 + i) * HD + tx * 4;
        #pragma unroll
        for (int j = 0; j < 4; j++)
            Out[rbase + j] = to_tf32(acc[i][j] * scale);
    }
}

// ---------------------------------------------------------------------------
// Kernel 2: flash attention via mma.sync tf32.
// grid = (NSEQ/128, NH), block = 256 (8 warps x 16 query rows).
// ---------------------------------------------------------------------------
__global__ __launch_bounds__(256, 2) void attn_kernel(const int* __restrict__ mask)
{
    extern __shared__ float smf[];
    float* Ks = smf;
    float* Vs = smf + SM_V;
    float* Ps = smf + SM_P;

    const int tid  = threadIdx.x;
    const int wid  = tid >> 5;
    const int lane = tid & 31;
    const int g = lane >> 2;    // groupID (row within fragment)
    const int t = lane & 3;     // threadID in group (col within fragment)

    const int h  = blockIdx.y;
    const int q0 = blockIdx.x * QT;
    const int wrow = wid * 16;  // warp's first query row within tile

    // ---- Stage Q tile (128x64) into smem (reuses K/V area), grab fragments ----
    {
        const float* Qg = g_Q + ((size_t)h * NSEQ + q0) * HD;
        for (int idx = tid; idx < 128 * 16; idx += 256) {
            int r = idx >> 4, c4 = (idx & 15) << 2;
            float4 v = *(const float4*)(Qg + (size_t)r * HD + c4);
            *(float4*)(smf + r * KV_STRIDE + c4) = v;
        }
    }
    __syncthreads();

    uint32_t qa[8][4];
    #pragma unroll
    for (int ks = 0; ks < 8; ks++) {
        const float* Qr = smf + (wrow + g) * KV_STRIDE + ks * 8 + t;
        qa[ks][0] = __float_as_uint(Qr[0]);
        qa[ks][1] = __float_as_uint(Qr[8 * KV_STRIDE]);
        qa[ks][2] = __float_as_uint(Qr[4]);
        qa[ks][3] = __float_as_uint(Qr[8 * KV_STRIDE + 4]);
    }

    float oacc[8][4];
    #pragma unroll
    for (int nb = 0; nb < 8; nb++)
        #pragma unroll
        for (int i = 0; i < 4; i++) oacc[nb][i] = 0.f;

    float m_lo = -3.0e38f, m_hi = -3.0e38f;
    float l_lo = 0.f, l_hi = 0.f;

    const int* mrow_lo = mask + ((size_t)h * NSEQ + q0 + wrow + g) * NSEQ;
    const int* mrow_hi = mrow_lo + (size_t)8 * NSEQ;

    for (int it = 0; it < NIT; it++) {
        const int k0 = it * KT;
        __syncthreads();   // previous iteration's K/V fully consumed (and Q frags read)

        // ---- cooperative load K,V tiles (64x64 each) ----
        {
            const float* Kg = g_K + ((size_t)h * NSEQ + k0) * HD;
            const float* Vg = g_V + ((size_t)h * NSEQ + k0) * HD;
            #pragma unroll
            for (int u = 0; u < 4; u++) {
                int idx = tid + u * 256;           // 0..1023
                int r = idx >> 4, c4 = (idx & 15) << 2;
                float4 kv = *(const float4*)(Kg + (size_t)r * HD + c4);
                *(float4*)(Ks + r * KV_STRIDE + c4) = kv;
                float4 vv = *(const float4*)(Vg + (size_t)r * HD + c4);
                *(float4*)(Vs + r * KV_STRIDE + c4) = vv;
            }
        }
        __syncthreads();

        // ---- S = Q @ K^T : 8 k-steps (head dim) x 8 n-blocks (keys) ----
        float sacc[8][4];
        #pragma unroll
        for (int nb = 0; nb < 8; nb++)
            #pragma unroll
            for (int i = 0; i < 4; i++) sacc[nb][i] = 0.f;

        #pragma unroll
        for (int ks = 0; ks < 8; ks++) {
            #pragma unroll
            for (int nb = 0; nb < 8; nb++) {
                // B[k=d][n=key] = K[key = nb*8+g][d = ks*8+t]
                const float* Kp = Ks + (nb * 8 + g) * KV_STRIDE + ks * 8 + t;
                uint32_t b0 = __float_as_uint(Kp[0]);
                uint32_t b1 = __float_as_uint(Kp[4]);
                mma8(sacc[nb], qa[ks], b0, b1);
            }
        }

        // ---- mask + online softmax ----
        float mx_lo = -3.0e38f, mx_hi = -3.0e38f;
        #pragma unroll
        for (int nb = 0; nb < 8; nb++) {
            int2 ml = *(const int2*)(mrow_lo + k0 + nb * 8 + 2 * t);
            int2 mh = *(const int2*)(mrow_hi + k0 + nb * 8 + 2 * t);
            sacc[nb][0] = ml.x ? sacc[nb][0] : -1e30f;
            sacc[nb][1] = ml.y ? sacc[nb][1] : -1e30f;
            sacc[nb][2] = mh.x ? sacc[nb][2] : -1e30f;
            sacc[nb][3] = mh.y ? sacc[nb][3] : -1e30f;
            mx_lo = fmaxf(mx_lo, fmaxf(sacc[nb][0], sacc[nb][1]));
            mx_hi = fmaxf(mx_hi, fmaxf(sacc[nb][2], sacc[nb][3]));
        }
        mx_lo = fmaxf(mx_lo, __shfl_xor_sync(0xffffffffu, mx_lo, 1));
        mx_lo = fmaxf(mx_lo, __shfl_xor_sync(0xffffffffu, mx_lo, 2));
        mx_hi = fmaxf(mx_hi, __shfl_xor_sync(0xffffffffu, mx_hi, 1));
        mx_hi = fmaxf(mx_hi, __shfl_xor_sync(0xffffffffu, mx_hi, 2));

        float mn_lo = fmaxf(m_lo, mx_lo);
        float mn_hi = fmaxf(m_hi, mx_hi);
        float corr_lo = __expf(m_lo - mn_lo);
        float corr_hi = __expf(m_hi - mn_hi);
        m_lo = mn_lo; m_hi = mn_hi;

        float s_lo = 0.f, s_hi = 0.f;
        #pragma unroll
        for (int nb = 0; nb < 8; nb++) {
            sacc[nb][0] = __expf(sacc[nb][0] - mn_lo);
            sacc[nb][1] = __expf(sacc[nb][1] - mn_lo);
            sacc[nb][2] = __expf(sacc[nb][2] - mn_hi);
            sacc[nb][3] = __expf(sacc[nb][3] - mn_hi);
            s_lo += sacc[nb][0] + sacc[nb][1];
            s_hi += sacc[nb][2] + sacc[nb][3];
        }
        s_lo += __shfl_xor_sync(0xffffffffu, s_lo, 1);
        s_lo += __shfl_xor_sync(0xffffffffu, s_lo, 2);
        s_hi += __shfl_xor_sync(0xffffffffu, s_hi, 1);
        s_hi += __shfl_xor_sync(0xffffffffu, s_hi, 2);
        l_lo = l_lo * corr_lo + s_lo;
        l_hi = l_hi * corr_hi + s_hi;

        // rescale O accumulator
        #pragma unroll
        for (int nb = 0; nb < 8; nb++) {
            oacc[nb][0] *= corr_lo; oacc[nb][1] *= corr_lo;
            oacc[nb][2] *= corr_hi; oacc[nb][3] *= corr_hi;
        }

        // ---- store P (tf32-rounded) to warp-private smem tile ----
        #pragma unroll
        for (int nb = 0; nb < 8; nb++) {
            float2 plo = make_float2(to_tf32(sacc[nb][0]), to_tf32(sacc[nb][1]));
            float2 phi = make_float2(to_tf32(sacc[nb][2]), to_tf32(sacc[nb][3]));
            *(float2*)(Ps + (wrow + g) * KV_STRIDE + nb * 8 + 2 * t)     = plo;
            *(float2*)(Ps + (wrow + g + 8) * KV_STRIDE + nb * 8 + 2 * t) = phi;
        }
        __syncwarp();

        // ---- O += P @ V : 8 k-steps (keys) x 8 n-blocks (head dim) ----
        #pragma unroll
        for (int ks = 0; ks < 8; ks++) {
            uint32_t pa[4];
            const float* Pp = Ps + (wrow + g) * KV_STRIDE + ks * 8 + t;
            pa[0] = __float_as_uint(Pp[0]);
            pa[1] = __float_as_uint(Pp[8 * KV_STRIDE]);
            pa[2] = __float_as_uint(Pp[4]);
            pa[3] = __float_as_uint(Pp[8 * KV_STRIDE + 4]);
            #pragma unroll
            for (int nb = 0; nb < 8; nb++) {
                // B[k=key][n=dim] = V[key = ks*8+t][dim = nb*8+g]
                const float* Vp = Vs + (ks * 8 + t) * KV_STRIDE + nb * 8 + g;
                uint32_t b0 = __float_as_uint(Vp[0]);
                uint32_t b1 = __float_as_uint(Vp[4 * KV_STRIDE]);
                mma8(oacc[nb], pa, b0, b1);
            }
        }
    }

    // ---- normalize, write Hcat ----
    float inv_lo = 1.f / l_lo;
    float inv_hi = 1.f / l_hi;
    float* Crow_lo = g_C + (size_t)(q0 + wrow + g) * (NH * HD) + h * HD;
    float* Crow_hi = Crow_lo + (size_t)8 * (NH * HD);
    #pragma unroll
    for (int nb = 0; nb < 8; nb++) {
        float2 lo = make_float2(oacc[nb][0] * inv_lo, oacc[nb][1] * inv_lo);
        float2 hi = make_float2(oacc[nb][2] * inv_hi, oacc[nb][3] * inv_hi);
        *(float2*)(Crow_lo + nb * 8 + 2 * t) = lo;
        *(float2*)(Crow_hi + nb * 8 + 2 * t) = hi;
    }
}

// ---------------------------------------------------------------------------
// Kernel 3: output projection (fp32 scalar)
// ---------------------------------------------------------------------------
__global__ __launch_bounds__(256) void proj_kernel(
    const float* __restrict__ Wo, float* __restrict__ out)
{
    __shared__ float Cs[64][33];
    __shared__ float Ws[64][33];

    const int m0 = blockIdx.x * 64;
    const int n0 = blockIdx.y * 64;
    const int tid = threadIdx.x;
    const int tx = tid & 15;
    const int ty = tid >> 4;

    float acc[4][4];
    #pragma unroll
    for (int i = 0; i < 4; i++)
        #pragma unroll
        for (int j = 0; j < 4; j++) acc[i][j] = 0.f;

    for (int f0 = 0; f0 < FIN; f0 += 32) {
        #pragma unroll
        for (int u = 0; u < 2; u++) {
            int idx = tid * 2 + u;
            int row = idx >> 3;
            int c4  = (idx & 7) * 4;
            float4 cv = *(const float4*)(g_C + (size_t)(m0 + row) * (NH * HD) + f0 + c4);
            Cs[row][c4 + 0] = cv.x; Cs[row][c4 + 1] = cv.y;
            Cs[row][c4 + 2] = cv.z; Cs[row][c4 + 3] = cv.w;
            float4 wv = *(const float4*)(Wo + (size_t)(n0 + row) * (NH * HD) + f0 + c4);
            Ws[row][c4 + 0] = wv.x; Ws[row][c4 + 1] = wv.y;
            Ws[row][c4 + 2] = wv.z; Ws[row][c4 + 3] = wv.w;
        }
        __syncthreads();
        #pragma unroll
        for (int kk = 0; kk < 32; kk++) {
            float a[4], b[4];
            #pragma unroll
            for (int i = 0; i < 4; i++) a[i] = Cs[ty * 4 + i][kk];
            #pragma unroll
            for (int j = 0; j < 4; j++) b[j] = Ws[tx * 4 + j][kk];
            #pragma unroll
            for (int i = 0; i < 4; i++)
                #pragma unroll
                for (int j = 0; j < 4; j++)
                    acc[i][j] = fmaf(a[i], b[j], acc[i][j]);
        }
        __syncthreads();
    }

    #pragma unroll
    for (int i = 0; i < 4; i++) {
        size_t rbase = (size_t)(m0 + ty * 4 + i) * FOUT + n0 + tx * 4;
        #pragma unroll
        for (int j = 0; j < 4; j++)
            out[rbase + j] = acc[i][j];
    }
}

// ---------------------------------------------------------------------------
extern "C" void kernel_launch(void* const* d_in, const int* in_sizes, int n_in,
                              void* d_out, int out_size)
{
    const float* X    = (const float*)d_in[0];
    const int*   mask = (const int*)  d_in[1];
    const float* Wq   = (const float*)d_in[2];
    const float* Wk   = (const float*)d_in[3];
    const float* Wv   = (const float*)d_in[4];
    const float* Wo   = (const float*)d_in[5];
    float*       out  = (float*)d_out;

    cudaFuncSetAttribute(attn_kernel,
                         cudaFuncAttributeMaxDynamicSharedMemorySize, ATTN_SMEM_BYTES);

    qkv_kernel<<<dim3(NSEQ / 64, NH, 3), 256>>>(X, Wq, Wk, Wv);
    attn_kernel<<<dim3(NSEQ / QT, NH), 256, ATTN_SMEM_BYTES>>>(mask);
    proj_kernel<<<dim3(NSEQ / 64, FOUT / 64), 256>>>(Wo, out);
}